// round 4
// baseline (speedup 1.0000x reference)
#include <cuda_runtime.h>
#include <cstdint>
#include <math_constants.h>

#define NHEADS 32
#define HD     128
#define NB     2
#define NS     2048
#define NH     4096
#define NTOK   (NB*NS)   // 4096 tokens

// ---------------- scratch (device globals: no allocations allowed) ----------
__device__ float g_q[(size_t)NB*NHEADS*NS*HD];    // [b][h][s][d]
__device__ float g_k[(size_t)NB*NHEADS*NS*HD];
__device__ float g_v[(size_t)NB*NHEADS*NS*HD];
__device__ float g_ctx[(size_t)NTOK*NH];          // token-major [b*s][h*d]

// ---------------- helpers ----------------------------------------------------
__device__ __forceinline__ float tf32f(float x) {
    unsigned u; asm("cvt.rna.tf32.f32 %0, %1;" : "=r"(u) : "f"(x));
    return __uint_as_float(u);
}

__device__ __forceinline__ void mma8(float* d, const unsigned* a, const unsigned* b) {
    asm volatile(
        "mma.sync.aligned.m16n8k8.row.col.f32.tf32.tf32.f32 "
        "{%0,%1,%2,%3}, {%4,%5,%6,%7}, {%8,%9}, {%0,%1,%2,%3};\n"
        : "+f"(d[0]), "+f"(d[1]), "+f"(d[2]), "+f"(d[3])
        : "r"(a[0]), "r"(a[1]), "r"(a[2]), "r"(a[3]), "r"(b[0]), "r"(b[1]));
}

__device__ __forceinline__ void scatter_qkv(int m, int n, float v) {
    // m = token row (0..4095), n = qkv column (0..12287)
    int b = m >> 11, s = m & 2047;
    int which = n >> 12, rem = n & 4095;
    int h = rem >> 7, d = rem & 127;
    size_t idx = ((((size_t)b * NHEADS + h) * NS) + s) * HD + d;
    float* dst = (which == 0) ? g_q : (which == 1) ? g_k : g_v;
    dst[idx] = v;
}

// ---------------- GEMM: C[M,N] = A[M,K] @ W[K,N] + bias ----------------------
// CTA tile 128x128, K-tile 32, 256 threads = 8 warps (4 m x 2 n),
// warp tile 32x64 -> 2 m16 tiles x 8 n8 tiles, tf32 mma, fp32 accum.
// MODE 0: A = param, epilogue scatters into g_q/g_k/g_v.
// MODE 1: A = g_ctx, epilogue writes C + bias.
template<int MODE>
__global__ __launch_bounds__(256, 2) void gemm_tf32(
    const float* __restrict__ A, const float* __restrict__ W,
    const float* __restrict__ bias, float* __restrict__ C,
    int M, int N, int K)
{
    __shared__ float As[128 * 36];   // [row][k], pad->stride 36: conflict-free frag reads
    __shared__ float Bs[32 * 136];   // [k][n],  pad->stride 136

    const int tid  = threadIdx.x;
    const int warp = tid >> 5, lane = tid & 31;
    const int wm = warp >> 1, wn = warp & 1;
    const int lq = lane & 3, lr = lane >> 2;
    const int brow = blockIdx.y * 128, bcol = blockIdx.x * 128;

    const float* Aptr = (MODE == 1) ? (const float*)g_ctx : A;

    float acc[2][8][4];
    #pragma unroll
    for (int mi = 0; mi < 2; mi++)
        #pragma unroll
        for (int ni = 0; ni < 8; ni++)
            #pragma unroll
            for (int j = 0; j < 4; j++) acc[mi][ni][j] = 0.f;

    const float* gA = Aptr + (size_t)brow * K;
    const float* gB = W + bcol;

    for (int kt = 0; kt < K; kt += 32) {
        // A tile 128x32: 1024 float4s over 256 threads
        #pragma unroll
        for (int i = 0; i < 4; i++) {
            int f = tid + i * 256;
            int row = f >> 3, c4 = (f & 7) << 2;
            float4 v = *(const float4*)(gA + (size_t)row * K + kt + c4);
            As[row * 36 + c4 + 0] = tf32f(v.x);
            As[row * 36 + c4 + 1] = tf32f(v.y);
            As[row * 36 + c4 + 2] = tf32f(v.z);
            As[row * 36 + c4 + 3] = tf32f(v.w);
        }
        // B tile 32x128
        #pragma unroll
        for (int i = 0; i < 4; i++) {
            int f = tid + i * 256;
            int row = f >> 5, c4 = (f & 31) << 2;
            float4 v = *(const float4*)(gB + (size_t)(kt + row) * N + c4);
            Bs[row * 136 + c4 + 0] = tf32f(v.x);
            Bs[row * 136 + c4 + 1] = tf32f(v.y);
            Bs[row * 136 + c4 + 2] = tf32f(v.z);
            Bs[row * 136 + c4 + 3] = tf32f(v.w);
        }
        __syncthreads();

        #pragma unroll
        for (int ks = 0; ks < 4; ks++) {
            const int k = ks * 8;
            unsigned af[2][4];
            #pragma unroll
            for (int mi = 0; mi < 2; mi++) {
                int r = wm * 32 + mi * 16 + lr;
                af[mi][0] = __float_as_uint(As[r * 36 + k + lq]);
                af[mi][1] = __float_as_uint(As[(r + 8) * 36 + k + lq]);
                af[mi][2] = __float_as_uint(As[r * 36 + k + lq + 4]);
                af[mi][3] = __float_as_uint(As[(r + 8) * 36 + k + lq + 4]);
            }
            #pragma unroll
            for (int ni = 0; ni < 8; ni++) {
                int n = wn * 64 + ni * 8 + lr;
                unsigned bf[2];
                bf[0] = __float_as_uint(Bs[(k + lq) * 136 + n]);
                bf[1] = __float_as_uint(Bs[(k + lq + 4) * 136 + n]);
                mma8(acc[0][ni], af[0], bf);
                mma8(acc[1][ni], af[1], bf);
            }
        }
        __syncthreads();
    }

    // epilogue
    #pragma unroll
    for (int mi = 0; mi < 2; mi++) {
        int r0 = brow + wm * 32 + mi * 16 + lr;
        #pragma unroll
        for (int ni = 0; ni < 8; ni++) {
            int c0 = bcol + wn * 64 + ni * 8 + 2 * lq;
            float v0 = acc[mi][ni][0] + bias[c0];
            float v1 = acc[mi][ni][1] + bias[c0 + 1];
            float v2 = acc[mi][ni][2] + bias[c0];
            float v3 = acc[mi][ni][3] + bias[c0 + 1];
            if (MODE == 0) {
                scatter_qkv(r0,     c0,     v0);
                scatter_qkv(r0,     c0 + 1, v1);
                scatter_qkv(r0 + 8, c0,     v2);
                scatter_qkv(r0 + 8, c0 + 1, v3);
            } else {
                C[(size_t)r0 * N + c0]           = v0;
                C[(size_t)r0 * N + c0 + 1]       = v1;
                C[(size_t)(r0 + 8) * N + c0]     = v2;
                C[(size_t)(r0 + 8) * N + c0 + 1] = v3;
            }
        }
    }
}

// ---------------- flash attention --------------------------------------------
// grid (S/64 q-tiles, B*HEADS), 128 threads = 4 warps; warp owns 16 q-rows.
// Per KV tile of 64: S = Q K^T (scale folded into Q), online softmax,
// P staged via smem, O += P V. tf32 mma, fp32 accum/softmax.
#define QS_STRIDE 132
#define KS_STRIDE 132
#define VS_STRIDE 136
#define PS_STRIDE 68
#define SM_K_OFF  (64 * QS_STRIDE)
#define SM_V_OFF  (SM_K_OFF + 64 * KS_STRIDE)
#define SM_P_OFF  (SM_V_OFF + 64 * VS_STRIDE)
#define SMEM_FLASH ((SM_P_OFF + 64 * PS_STRIDE) * 4)

__global__ __launch_bounds__(128, 1) void flash_attn()
{
    extern __shared__ float sm[];
    float* Qs = sm;
    float* Ks = sm + SM_K_OFF;
    float* Vs = sm + SM_V_OFF;
    float* Ps = sm + SM_P_OFF;

    const int tid = threadIdx.x, warp = tid >> 5, lane = tid & 31;
    const int lq = lane & 3, lr = lane >> 2;
    const int bh = blockIdx.y, qt = blockIdx.x;
    const float scale = 0.08838834764831845f;  // 1/sqrt(128)

    const float* Qg = g_q + ((size_t)bh * NS + qt * 64) * HD;
    const float* Kg = g_k + (size_t)bh * NS * HD;
    const float* Vg = g_v + (size_t)bh * NS * HD;

    // load Q tile (pre-scaled, tf32-rounded)
    #pragma unroll
    for (int i = 0; i < 16; i++) {
        int f = tid + i * 128;
        int row = f >> 5, c4 = (f & 31) << 2;
        float4 v = *(const float4*)(Qg + (size_t)row * HD + c4);
        Qs[row * QS_STRIDE + c4 + 0] = tf32f(v.x * scale);
        Qs[row * QS_STRIDE + c4 + 1] = tf32f(v.y * scale);
        Qs[row * QS_STRIDE + c4 + 2] = tf32f(v.z * scale);
        Qs[row * QS_STRIDE + c4 + 3] = tf32f(v.w * scale);
    }

    float oacc[16][4];
    #pragma unroll
    for (int ni = 0; ni < 16; ni++)
        #pragma unroll
        for (int j = 0; j < 4; j++) oacc[ni][j] = 0.f;

    float m0 = -CUDART_INF_F, m1 = -CUDART_INF_F, l0 = 0.f, l1 = 0.f;
    const int r = warp * 16 + lr;

    for (int kt = 0; kt < NS / 64; kt++) {
        __syncthreads();   // prior PV done before overwriting K/V
        #pragma unroll
        for (int i = 0; i < 16; i++) {
            int f = tid + i * 128;
            int row = f >> 5, c4 = (f & 31) << 2;
            float4 kv = *(const float4*)(Kg + (size_t)(kt * 64 + row) * HD + c4);
            Ks[row * KS_STRIDE + c4 + 0] = tf32f(kv.x);
            Ks[row * KS_STRIDE + c4 + 1] = tf32f(kv.y);
            Ks[row * KS_STRIDE + c4 + 2] = tf32f(kv.z);
            Ks[row * KS_STRIDE + c4 + 3] = tf32f(kv.w);
            float4 vv = *(const float4*)(Vg + (size_t)(kt * 64 + row) * HD + c4);
            Vs[row * VS_STRIDE + c4 + 0] = tf32f(vv.x);
            Vs[row * VS_STRIDE + c4 + 1] = tf32f(vv.y);
            Vs[row * VS_STRIDE + c4 + 2] = tf32f(vv.z);
            Vs[row * VS_STRIDE + c4 + 3] = tf32f(vv.w);
        }
        __syncthreads();

        // S = Q K^T  (warp: 16 rows x 64 kv-cols)
        float sacc[8][4];
        #pragma unroll
        for (int ni = 0; ni < 8; ni++)
            #pragma unroll
            for (int j = 0; j < 4; j++) sacc[ni][j] = 0.f;

        #pragma unroll
        for (int ks = 0; ks < 16; ks++) {
            int k = ks * 8;
            unsigned qa[4];
            qa[0] = __float_as_uint(Qs[r * QS_STRIDE + k + lq]);
            qa[1] = __float_as_uint(Qs[(r + 8) * QS_STRIDE + k + lq]);
            qa[2] = __float_as_uint(Qs[r * QS_STRIDE + k + lq + 4]);
            qa[3] = __float_as_uint(Qs[(r + 8) * QS_STRIDE + k + lq + 4]);
            #pragma unroll
            for (int ni = 0; ni < 8; ni++) {
                int j = ni * 8 + lr;
                unsigned kb[2];
                kb[0] = __float_as_uint(Ks[j * KS_STRIDE + k + lq]);
                kb[1] = __float_as_uint(Ks[j * KS_STRIDE + k + lq + 4]);
                mma8(sacc[ni], qa, kb);
            }
        }

        // online softmax (rows r and r+8; row stats replicated across quad)
        float mt0 = -CUDART_INF_F, mt1 = -CUDART_INF_F;
        #pragma unroll
        for (int ni = 0; ni < 8; ni++) {
            mt0 = fmaxf(mt0, fmaxf(sacc[ni][0], sacc[ni][1]));
            mt1 = fmaxf(mt1, fmaxf(sacc[ni][2], sacc[ni][3]));
        }
        mt0 = fmaxf(mt0, __shfl_xor_sync(0xffffffffu, mt0, 1));
        mt0 = fmaxf(mt0, __shfl_xor_sync(0xffffffffu, mt0, 2));
        mt1 = fmaxf(mt1, __shfl_xor_sync(0xffffffffu, mt1, 1));
        mt1 = fmaxf(mt1, __shfl_xor_sync(0xffffffffu, mt1, 2));

        float mn0 = fmaxf(m0, mt0), mn1 = fmaxf(m1, mt1);
        float a0 = __expf(m0 - mn0), a1 = __expf(m1 - mn1);

        float sum0 = 0.f, sum1 = 0.f;
        #pragma unroll
        for (int ni = 0; ni < 8; ni++) {
            int c = ni * 8 + 2 * lq;
            float p0 = __expf(sacc[ni][0] - mn0);
            float p1 = __expf(sacc[ni][1] - mn0);
            float p2 = __expf(sacc[ni][2] - mn1);
            float p3 = __expf(sacc[ni][3] - mn1);
            sum0 += p0 + p1;  sum1 += p2 + p3;
            Ps[r * PS_STRIDE + c]           = tf32f(p0);
            Ps[r * PS_STRIDE + c + 1]       = tf32f(p1);
            Ps[(r + 8) * PS_STRIDE + c]     = tf32f(p2);
            Ps[(r + 8) * PS_STRIDE + c + 1] = tf32f(p3);
        }
        sum0 += __shfl_xor_sync(0xffffffffu, sum0, 1);
        sum0 += __shfl_xor_sync(0xffffffffu, sum0, 2);
        sum1 += __shfl_xor_sync(0xffffffffu, sum1, 1);
        sum1 += __shfl_xor_sync(0xffffffffu, sum1, 2);

        l0 = l0 * a0 + sum0;
        l1 = l1 * a1 + sum1;
        m0 = mn0; m1 = mn1;

        #pragma unroll
        for (int ni = 0; ni < 16; ni++) {
            oacc[ni][0] *= a0; oacc[ni][1] *= a0;
            oacc[ni][2] *= a1; oacc[ni][3] *= a1;
        }
        __syncwarp();  // order P smem writes before same-warp frag reads

        // O += P V   (warp: 16 rows x 128 d-cols, k=64)
        #pragma unroll
        for (int ks = 0; ks < 8; ks++) {
            int k = ks * 8;
            unsigned pa[4];
            pa[0] = __float_as_uint(Ps[r * PS_STRIDE + k + lq]);
            pa[1] = __float_as_uint(Ps[(r + 8) * PS_STRIDE + k + lq]);
            pa[2] = __float_as_uint(Ps[r * PS_STRIDE + k + lq + 4]);
            pa[3] = __float_as_uint(Ps[(r + 8) * PS_STRIDE + k + lq + 4]);
            #pragma unroll
            for (int ni = 0; ni < 16; ni++) {
                int n = ni * 8 + lr;
                unsigned vb[2];
                vb[0] = __float_as_uint(Vs[(k + lq) * VS_STRIDE + n]);
                vb[1] = __float_as_uint(Vs[(k + lq + 4) * VS_STRIDE + n]);
                mma8(oacc[ni], pa, vb);
            }
        }
    }

    // epilogue: normalize and write ctx token-major
    float inv0 = 1.f / l0, inv1 = 1.f / l1;
    int b = bh >> 5, h = bh & 31;
    int row0 = qt * 64 + r;
    size_t tok0 = ((size_t)b * NS + row0) * NH;
    size_t tok1 = ((size_t)b * NS + row0 + 8) * NH;
    #pragma unroll
    for (int ni = 0; ni < 16; ni++) {
        int col = h * HD + ni * 8 + 2 * lq;
        g_ctx[tok0 + col]     = oacc[ni][0] * inv0;
        g_ctx[tok0 + col + 1] = oacc[ni][1] * inv0;
        g_ctx[tok1 + col]     = oacc[ni][2] * inv1;
        g_ctx[tok1 + col + 1] = oacc[ni][3] * inv1;
    }
}

// ---------------- launch ------------------------------------------------------
extern "C" void kernel_launch(void* const* d_in, const int* in_sizes, int n_in,
                              void* d_out, int out_size)
{
    const float* x    = (const float*)d_in[0];
    const float* wqkv = (const float*)d_in[1];
    const float* bqkv = (const float*)d_in[2];
    const float* wo   = (const float*)d_in[3];
    const float* bo   = (const float*)d_in[4];
    float* out = (float*)d_out;

    cudaFuncSetAttribute(flash_attn, cudaFuncAttributeMaxDynamicSharedMemorySize, SMEM_FLASH);

    // 1) QKV GEMM + bias, scattered into [b][h][s][d] Q/K/V
    gemm_tf32<0><<<dim3(3 * NH / 128, NTOK / 128), 256>>>(
        x, wqkv, bqkv, nullptr, NTOK, 3 * NH, NH);

    // 2) flash attention -> ctx (token-major)
    flash_attn<<<dim3(NS / 64, NB * NHEADS), 128, SMEM_FLASH>>>();

    // 3) output projection + bias
    gemm_tf32<1><<<dim3(NH / 128, NTOK / 128), 256>>>(
        nullptr, wo, bo, out, NTOK, NH, NH);
}